// round 2
// baseline (speedup 1.0000x reference)
#include <cuda_runtime.h>
#include <math.h>

// Problem shape (fixed by the dataset)
#define B_DIM 256
#define K_DIM 512
#define D_DIM 1024
#define KPB   64                      // k rows per block (8 warps x 8 rows)
#define NBLK  (B_DIM * (K_DIM / KPB)) // 2048 blocks
#define INV_T 14.2857142857142857f    // 1/0.07

// Scratch (no allocations allowed). Partials are fully overwritten every
// launch; the ticket counter returns to 0 at the end of every launch, so
// the kernel is idempotent under graph replay.
__device__ double2       g_part[NBLK];   // {pos_part, fg_part} per block
__device__ unsigned int  g_ticket;       // zero-initialized at module load

__global__ __launch_bounds__(256)
void fused_kernel(const float* __restrict__ bg_img,
                  const float* __restrict__ fg_pro,
                  const float* __restrict__ bg_pro,
                  float* __restrict__ out) {
    const int b    = blockIdx.x;
    const int ky   = blockIdx.y;
    const int warp = threadIdx.x >> 5;
    const int lane = threadIdx.x & 31;

    // ---- load query row into registers; q[i] = row[i*128 + lane*4 .. +3] ----
    float4 q[8];
    const float4* qrow = reinterpret_cast<const float4*>(bg_img + (size_t)b * D_DIM);
    float ss = 0.f;
    #pragma unroll
    for (int i = 0; i < 8; i++) {
        float4 v = qrow[i * 32 + lane];
        ss = fmaf(v.x, v.x, ss);
        ss = fmaf(v.y, v.y, ss);
        ss = fmaf(v.z, v.z, ss);
        ss = fmaf(v.w, v.w, ss);
        q[i] = v;
    }
    #pragma unroll
    for (int o = 16; o; o >>= 1) ss += __shfl_xor_sync(0xFFFFFFFFu, ss, o);
    const float inv = 1.0f / sqrtf(ss);
    #pragma unroll
    for (int i = 0; i < 8; i++) {
        q[i].x *= inv; q[i].y *= inv; q[i].z *= inv; q[i].w *= inv;
    }

    // ---- fg contribution: one warp per batch row (ky==0, warp 0) ----
    __shared__ double s_fg;
    if (threadIdx.x == 0) s_fg = 0.0;
    if (ky == 0 && warp == 0) {
        const float4* frow = reinterpret_cast<const float4*>(fg_pro + (size_t)b * D_DIM);
        float fd = 0.f;
        #pragma unroll
        for (int i = 0; i < 8; i++) {
            float4 f = frow[i * 32 + lane];
            fd = fmaf(q[i].x, f.x, fd);
            fd = fmaf(q[i].y, f.y, fd);
            fd = fmaf(q[i].z, f.z, fd);
            fd = fmaf(q[i].w, f.w, fd);
        }
        #pragma unroll
        for (int o = 16; o; o >>= 1) fd += __shfl_xor_sync(0xFFFFFFFFu, fd, o);
        if (lane == 0) s_fg = (double)expf(fd * INV_T);
    }

    // ---- main streaming loop: this warp owns 8 consecutive k rows ----
    const int k0 = ky * KPB + warp * 8;
    const float4* prow =
        reinterpret_cast<const float4*>(bg_pro + ((size_t)b * K_DIM + k0) * D_DIM);

    double acc = 0.0;
    #pragma unroll
    for (int kk = 0; kk < 8; kk++) {
        const float4* p = prow + (size_t)kk * (D_DIM / 4);
        float s = 0.f;
        #pragma unroll
        for (int i = 0; i < 8; i++) {
            float4 pv = p[i * 32 + lane];
            s = fmaf(q[i].x, pv.x, s);
            s = fmaf(q[i].y, pv.y, s);
            s = fmaf(q[i].z, pv.z, s);
            s = fmaf(q[i].w, pv.w, s);
        }
        #pragma unroll
        for (int o = 16; o; o >>= 1) s += __shfl_xor_sync(0xFFFFFFFFu, s, o);
        if (lane == 0) acc += (double)expf(s * INV_T);
    }

    // ---- block reduce of pos partials ----
    __shared__ double sacc[8];
    if (lane == 0) sacc[warp] = acc;
    __syncthreads();

    const int blk = blockIdx.y * gridDim.x + blockIdx.x;
    __shared__ bool s_is_last;
    if (threadIdx.x == 0) {
        double t = 0.0;
        #pragma unroll
        for (int i = 0; i < 8; i++) t += sacc[i];
        g_part[blk] = make_double2(t, s_fg);
        __threadfence();
        unsigned int done = atomicAdd(&g_ticket, 1u);
        s_is_last = (done == (unsigned int)(NBLK - 1));
    }
    __syncthreads();

    // ---- last block: reduce all partials, write output, reset ticket ----
    if (s_is_last) {
        const volatile double* vp = reinterpret_cast<const volatile double*>(g_part);
        double pos = 0.0, fg = 0.0;
        for (int i = threadIdx.x; i < NBLK; i += 256) {
            pos += vp[2 * i + 0];
            fg  += vp[2 * i + 1];
        }
        #pragma unroll
        for (int o = 16; o; o >>= 1) {
            pos += __shfl_xor_sync(0xFFFFFFFFu, pos, o);
            fg  += __shfl_xor_sync(0xFFFFFFFFu, fg,  o);
        }
        __shared__ double w_pos[8], w_fg[8];
        if (lane == 0) { w_pos[warp] = pos; w_fg[warp] = fg; }
        __syncthreads();
        if (threadIdx.x == 0) {
            double P = 0.0, F = 0.0;
            #pragma unroll
            for (int i = 0; i < 8; i++) { P += w_pos[i]; F += w_fg[i]; }
            // -log(pos/neg) = log1p(K * F / S), S = sum exp(bg), F = sum exp(fg)
            out[0] = (float)log1p(F * (double)K_DIM / P);
            g_ticket = 0;   // restore for next graph replay
        }
    }
}

extern "C" void kernel_launch(void* const* d_in, const int* in_sizes, int n_in,
                              void* d_out, int out_size) {
    const float* bg_img = (const float*)d_in[0];   // [B, D]
    const float* fg_pro = (const float*)d_in[1];   // [B, D]
    const float* bg_pro = (const float*)d_in[2];   // [B, K, D]
    float* out = (float*)d_out;

    dim3 grid(B_DIM, K_DIM / KPB);
    fused_kernel<<<grid, 256>>>(bg_img, fg_pro, bg_pro, out);
}